// round 1
// baseline (speedup 1.0000x reference)
#include <cuda_runtime.h>
#include <math.h>

#define NROWS 50000
#define DIN   1024
#define DC    512
#define DH    256

// Scratch for intermediates (allocation-free rule: __device__ globals)
__device__ float g_tv[NROWS * DH];
__device__ float g_tu[NROWS * DH];
__device__ float g_v [NROWS * DH];
__device__ float g_u [NROWS * DH];

// ----------------------------------------------------------------------------
// Tiled SGEMM: C[M,N] = act(A[M,K] @ B[K,N] + bias[N])
// BM=128, BN=128, BK=16, 256 threads, 8x8 per-thread micro-tile.
// ACT: 0=none, 1=relu, 2=tanh, 3=sigmoid
// Requires: K % 16 == 0, N % 128 == 0 (true for all shapes here). M guarded.
// ----------------------------------------------------------------------------
template<int ACT>
__global__ __launch_bounds__(256, 2)
void sgemm_bias_act(const float* __restrict__ A, const float* __restrict__ B,
                    const float* __restrict__ bias, float* __restrict__ C,
                    int M, int N, int K)
{
    const int BM = 128, BN = 128, BK = 16;
    __shared__ float As[BK][BM + 4];   // +4 pad: keeps 16B alignment, kills STS conflicts
    __shared__ float Bs[BK][BN];

    const int tid = threadIdx.x;
    const int tx  = tid & 15;          // 0..15 -> output col group (8 cols each)
    const int ty  = tid >> 4;          // 0..15 -> output row group (8 rows each)
    const int bm  = blockIdx.y * BM;
    const int bn  = blockIdx.x * BN;

    float acc[8][8];
    #pragma unroll
    for (int i = 0; i < 8; i++)
        #pragma unroll
        for (int j = 0; j < 8; j++) acc[i][j] = 0.0f;

    for (int k0 = 0; k0 < K; k0 += BK) {
        // ---- load A tile (BM x BK), store transposed into As[k][m] ----
        #pragma unroll
        for (int l = 0; l < 2; l++) {
            int gid = tid + l * 256;       // 0..511
            int row = gid >> 2;            // 0..127
            int kc  = (gid & 3) << 2;      // 0,4,8,12
            float4 va = make_float4(0.f, 0.f, 0.f, 0.f);
            int grow = bm + row;
            if (grow < M)
                va = *reinterpret_cast<const float4*>(&A[(size_t)grow * K + k0 + kc]);
            As[kc + 0][row] = va.x;
            As[kc + 1][row] = va.y;
            As[kc + 2][row] = va.z;
            As[kc + 3][row] = va.w;
        }
        // ---- load B tile (BK x BN), coalesced float4 along N ----
        #pragma unroll
        for (int l = 0; l < 2; l++) {
            int gid = tid + l * 256;       // 0..511
            int rk  = gid >> 5;            // 0..15
            int nc  = (gid & 31) << 2;     // 0..124
            float4 vb = *reinterpret_cast<const float4*>(&B[(size_t)(k0 + rk) * N + bn + nc]);
            *reinterpret_cast<float4*>(&Bs[rk][nc]) = vb;
        }
        __syncthreads();

        // ---- 8x8 micro-tile FMA over BK ----
        #pragma unroll
        for (int kk = 0; kk < BK; kk++) {
            float a[8], b[8];
            *reinterpret_cast<float4*>(&a[0]) = *reinterpret_cast<float4*>(&As[kk][ty * 8]);
            *reinterpret_cast<float4*>(&a[4]) = *reinterpret_cast<float4*>(&As[kk][ty * 8 + 4]);
            *reinterpret_cast<float4*>(&b[0]) = *reinterpret_cast<float4*>(&Bs[kk][tx * 8]);
            *reinterpret_cast<float4*>(&b[4]) = *reinterpret_cast<float4*>(&Bs[kk][tx * 8 + 4]);
            #pragma unroll
            for (int i = 0; i < 8; i++)
                #pragma unroll
                for (int j = 0; j < 8; j++)
                    acc[i][j] = fmaf(a[i], b[j], acc[i][j]);
        }
        __syncthreads();
    }

    // ---- epilogue: bias + activation + guarded vectorized store ----
    float bb[8];
    *reinterpret_cast<float4*>(&bb[0]) = *reinterpret_cast<const float4*>(&bias[bn + tx * 8]);
    *reinterpret_cast<float4*>(&bb[4]) = *reinterpret_cast<const float4*>(&bias[bn + tx * 8 + 4]);

    #pragma unroll
    for (int i = 0; i < 8; i++) {
        int grow = bm + ty * 8 + i;
        if (grow >= M) continue;
        float out[8];
        #pragma unroll
        for (int j = 0; j < 8; j++) {
            float c = acc[i][j] + bb[j];
            if (ACT == 1)      c = fmaxf(c, 0.0f);
            else if (ACT == 2) c = tanhf(c);
            else if (ACT == 3) c = 1.0f / (1.0f + expf(-c));
            out[j] = c;
        }
        *reinterpret_cast<float4*>(&C[(size_t)grow * N + bn + tx * 8])     = *reinterpret_cast<float4*>(&out[0]);
        *reinterpret_cast<float4*>(&C[(size_t)grow * N + bn + tx * 8 + 4]) = *reinterpret_cast<float4*>(&out[4]);
    }
}

// ----------------------------------------------------------------------------
// A[row, :] = (v[row,:] * u[row,:]) @ Wf[256,2] + bf[2]   (warp per row)
// ----------------------------------------------------------------------------
__global__ void gated_final(const float* __restrict__ v, const float* __restrict__ u,
                            const float* __restrict__ Wf, const float* __restrict__ bf,
                            float* __restrict__ out, int M)
{
    int row = blockIdx.x * blockDim.y + threadIdx.y;
    if (row >= M) return;
    int lane = threadIdx.x;

    const float* vr = v + (size_t)row * DH;
    const float* ur = u + (size_t)row * DH;

    float a0 = 0.f, a1 = 0.f;
    #pragma unroll
    for (int c = lane; c < DH; c += 32) {
        float g = vr[c] * ur[c];
        a0 = fmaf(g, Wf[c * 2 + 0], a0);
        a1 = fmaf(g, Wf[c * 2 + 1], a1);
    }
    #pragma unroll
    for (int off = 16; off; off >>= 1) {
        a0 += __shfl_down_sync(0xffffffffu, a0, off);
        a1 += __shfl_down_sync(0xffffffffu, a1, off);
    }
    if (lane == 0) {
        out[(size_t)row * 2 + 0] = a0 + bf[0];
        out[(size_t)row * 2 + 1] = a1 + bf[1];
    }
}

extern "C" void kernel_launch(void* const* d_in, const int* in_sizes, int n_in,
                              void* d_out, int out_size)
{
    (void)in_sizes; (void)n_in; (void)out_size;
    const float* X   = (const float*)d_in[0];
    const float* Wc  = (const float*)d_in[1];
    const float* bc  = (const float*)d_in[2];
    const float* Wv1 = (const float*)d_in[3];
    const float* bv1 = (const float*)d_in[4];
    const float* Wv2 = (const float*)d_in[5];
    const float* bv2 = (const float*)d_in[6];
    const float* Wu1 = (const float*)d_in[7];
    const float* bu1 = (const float*)d_in[8];
    const float* Wu2 = (const float*)d_in[9];
    const float* bu2 = (const float*)d_in[10];
    const float* Wf  = (const float*)d_in[11];
    const float* bf  = (const float*)d_in[12];

    float* h = (float*)d_out;                               // [N, 512]
    float* A = (float*)d_out + (size_t)NROWS * DC;          // [N, 2]

    float *tv, *tu, *vv, *uu;
    cudaGetSymbolAddress((void**)&tv, g_tv);
    cudaGetSymbolAddress((void**)&tu, g_tu);
    cudaGetSymbolAddress((void**)&vv, g_v);
    cudaGetSymbolAddress((void**)&uu, g_u);

    dim3 blk(256);
    int mblocks = (NROWS + 127) / 128;

    // h = relu(X @ Wc + bc)           [50000,1024]x[1024,512]
    sgemm_bias_act<1><<<dim3(DC / 128, mblocks), blk>>>(X, Wc, bc, h, NROWS, DC, DIN);
    // tv = h @ Wv1 + bv1 ; tu = h @ Wu1 + bu1    [50000,512]x[512,256]
    sgemm_bias_act<0><<<dim3(DH / 128, mblocks), blk>>>(h, Wv1, bv1, tv, NROWS, DH, DC);
    sgemm_bias_act<0><<<dim3(DH / 128, mblocks), blk>>>(h, Wu1, bu1, tu, NROWS, DH, DC);
    // v = tanh(tv @ Wv2 + bv2) ; u = sigmoid(tu @ Wu2 + bu2)   [50000,256]x[256,256]
    sgemm_bias_act<2><<<dim3(DH / 128, mblocks), blk>>>(tv, Wv2, bv2, vv, NROWS, DH, DH);
    sgemm_bias_act<3><<<dim3(DH / 128, mblocks), blk>>>(tu, Wu2, bu2, uu, NROWS, DH, DH);
    // A = (v*u) @ Wf + bf
    dim3 fb(32, 8);
    gated_final<<<(NROWS + 7) / 8, fb>>>(vv, uu, Wf, bf, A, NROWS);
}

// round 2
// speedup vs baseline: 1.0040x; 1.0040x over previous
#include <cuda_runtime.h>
#include <math.h>

#define NROWS 50000
#define DIN   1024
#define DC    512
#define DH    256

// Scratch for intermediates (allocation-free rule: __device__ globals)
__device__ float g_tv[NROWS * DH];
__device__ float g_tu[NROWS * DH];
__device__ float g_v [NROWS * DH];
__device__ float g_u [NROWS * DH];

// ----------------------------------------------------------------------------
// Tiled SGEMM: C[M,N] = act(A[M,K] @ B[K,N] + bias[N])
// BM=128, BN=128, BK=16, 256 threads, 8x8 per-thread micro-tile.
// ACT: 0=none, 1=relu, 2=tanh, 3=sigmoid
// Requires: K % 16 == 0, N % 128 == 0 (true for all shapes here). M guarded.
// ----------------------------------------------------------------------------
template<int ACT>
__global__ __launch_bounds__(256, 2)
void sgemm_bias_act(const float* __restrict__ A, const float* __restrict__ B,
                    const float* __restrict__ bias, float* __restrict__ C,
                    int M, int N, int K)
{
    const int BM = 128, BN = 128, BK = 16;
    __shared__ float As[BK][BM + 4];   // +4 pad: keeps 16B alignment, kills STS conflicts
    __shared__ float Bs[BK][BN];

    const int tid = threadIdx.x;
    const int tx  = tid & 15;          // 0..15 -> output col group (8 cols each)
    const int ty  = tid >> 4;          // 0..15 -> output row group (8 rows each)
    const int bm  = blockIdx.y * BM;
    const int bn  = blockIdx.x * BN;

    float acc[8][8];
    #pragma unroll
    for (int i = 0; i < 8; i++)
        #pragma unroll
        for (int j = 0; j < 8; j++) acc[i][j] = 0.0f;

    for (int k0 = 0; k0 < K; k0 += BK) {
        // ---- load A tile (BM x BK), store transposed into As[k][m] ----
        #pragma unroll
        for (int l = 0; l < 2; l++) {
            int gid = tid + l * 256;       // 0..511
            int row = gid >> 2;            // 0..127
            int kc  = (gid & 3) << 2;      // 0,4,8,12
            float4 va = make_float4(0.f, 0.f, 0.f, 0.f);
            int grow = bm + row;
            if (grow < M)
                va = *reinterpret_cast<const float4*>(&A[(size_t)grow * K + k0 + kc]);
            As[kc + 0][row] = va.x;
            As[kc + 1][row] = va.y;
            As[kc + 2][row] = va.z;
            As[kc + 3][row] = va.w;
        }
        // ---- load B tile (BK x BN), coalesced float4 along N ----
        #pragma unroll
        for (int l = 0; l < 2; l++) {
            int gid = tid + l * 256;       // 0..511
            int rk  = gid >> 5;            // 0..15
            int nc  = (gid & 31) << 2;     // 0..124
            float4 vb = *reinterpret_cast<const float4*>(&B[(size_t)(k0 + rk) * N + bn + nc]);
            *reinterpret_cast<float4*>(&Bs[rk][nc]) = vb;
        }
        __syncthreads();

        // ---- 8x8 micro-tile FMA over BK ----
        #pragma unroll
        for (int kk = 0; kk < BK; kk++) {
            float a[8], b[8];
            *reinterpret_cast<float4*>(&a[0]) = *reinterpret_cast<float4*>(&As[kk][ty * 8]);
            *reinterpret_cast<float4*>(&a[4]) = *reinterpret_cast<float4*>(&As[kk][ty * 8 + 4]);
            *reinterpret_cast<float4*>(&b[0]) = *reinterpret_cast<float4*>(&Bs[kk][tx * 8]);
            *reinterpret_cast<float4*>(&b[4]) = *reinterpret_cast<float4*>(&Bs[kk][tx * 8 + 4]);
            #pragma unroll
            for (int i = 0; i < 8; i++)
                #pragma unroll
                for (int j = 0; j < 8; j++)
                    acc[i][j] = fmaf(a[i], b[j], acc[i][j]);
        }
        __syncthreads();
    }

    // ---- epilogue: bias + activation + guarded vectorized store ----
    float bb[8];
    *reinterpret_cast<float4*>(&bb[0]) = *reinterpret_cast<const float4*>(&bias[bn + tx * 8]);
    *reinterpret_cast<float4*>(&bb[4]) = *reinterpret_cast<const float4*>(&bias[bn + tx * 8 + 4]);

    #pragma unroll
    for (int i = 0; i < 8; i++) {
        int grow = bm + ty * 8 + i;
        if (grow >= M) continue;
        float out[8];
        #pragma unroll
        for (int j = 0; j < 8; j++) {
            float c = acc[i][j] + bb[j];
            if (ACT == 1)      c = fmaxf(c, 0.0f);
            else if (ACT == 2) c = tanhf(c);
            else if (ACT == 3) c = 1.0f / (1.0f + expf(-c));
            out[j] = c;
        }
        *reinterpret_cast<float4*>(&C[(size_t)grow * N + bn + tx * 8])     = *reinterpret_cast<float4*>(&out[0]);
        *reinterpret_cast<float4*>(&C[(size_t)grow * N + bn + tx * 8 + 4]) = *reinterpret_cast<float4*>(&out[4]);
    }
}

// ----------------------------------------------------------------------------
// A[row, :] = (v[row,:] * u[row,:]) @ Wf[256,2] + bf[2]   (warp per row)
// ----------------------------------------------------------------------------
__global__ void gated_final(const float* __restrict__ v, const float* __restrict__ u,
                            const float* __restrict__ Wf, const float* __restrict__ bf,
                            float* __restrict__ out, int M)
{
    int row = blockIdx.x * blockDim.y + threadIdx.y;
    if (row >= M) return;
    int lane = threadIdx.x;

    const float* vr = v + (size_t)row * DH;
    const float* ur = u + (size_t)row * DH;

    float a0 = 0.f, a1 = 0.f;
    #pragma unroll
    for (int c = lane; c < DH; c += 32) {
        float g = vr[c] * ur[c];
        a0 = fmaf(g, Wf[c * 2 + 0], a0);
        a1 = fmaf(g, Wf[c * 2 + 1], a1);
    }
    #pragma unroll
    for (int off = 16; off; off >>= 1) {
        a0 += __shfl_down_sync(0xffffffffu, a0, off);
        a1 += __shfl_down_sync(0xffffffffu, a1, off);
    }
    if (lane == 0) {
        out[(size_t)row * 2 + 0] = a0 + bf[0];
        out[(size_t)row * 2 + 1] = a1 + bf[1];
    }
}

extern "C" void kernel_launch(void* const* d_in, const int* in_sizes, int n_in,
                              void* d_out, int out_size)
{
    (void)in_sizes; (void)n_in; (void)out_size;
    const float* X   = (const float*)d_in[0];
    const float* Wc  = (const float*)d_in[1];
    const float* bc  = (const float*)d_in[2];
    const float* Wv1 = (const float*)d_in[3];
    const float* bv1 = (const float*)d_in[4];
    const float* Wv2 = (const float*)d_in[5];
    const float* bv2 = (const float*)d_in[6];
    const float* Wu1 = (const float*)d_in[7];
    const float* bu1 = (const float*)d_in[8];
    const float* Wu2 = (const float*)d_in[9];
    const float* bu2 = (const float*)d_in[10];
    const float* Wf  = (const float*)d_in[11];
    const float* bf  = (const float*)d_in[12];

    float* h = (float*)d_out;                               // [N, 512]
    float* A = (float*)d_out + (size_t)NROWS * DC;          // [N, 2]

    float *tv, *tu, *vv, *uu;
    cudaGetSymbolAddress((void**)&tv, g_tv);
    cudaGetSymbolAddress((void**)&tu, g_tu);
    cudaGetSymbolAddress((void**)&vv, g_v);
    cudaGetSymbolAddress((void**)&uu, g_u);

    dim3 blk(256);
    int mblocks = (NROWS + 127) / 128;

    // h = relu(X @ Wc + bc)           [50000,1024]x[1024,512]
    sgemm_bias_act<1><<<dim3(DC / 128, mblocks), blk>>>(X, Wc, bc, h, NROWS, DC, DIN);
    // tv = h @ Wv1 + bv1 ; tu = h @ Wu1 + bu1    [50000,512]x[512,256]
    sgemm_bias_act<0><<<dim3(DH / 128, mblocks), blk>>>(h, Wv1, bv1, tv, NROWS, DH, DC);
    sgemm_bias_act<0><<<dim3(DH / 128, mblocks), blk>>>(h, Wu1, bu1, tu, NROWS, DH, DC);
    // v = tanh(tv @ Wv2 + bv2) ; u = sigmoid(tu @ Wu2 + bu2)   [50000,256]x[256,256]
    sgemm_bias_act<2><<<dim3(DH / 128, mblocks), blk>>>(tv, Wv2, bv2, vv, NROWS, DH, DH);
    sgemm_bias_act<3><<<dim3(DH / 128, mblocks), blk>>>(tu, Wu2, bu2, uu, NROWS, DH, DH);
    // A = (v*u) @ Wf + bf
    dim3 fb(32, 8);
    gated_final<<<(NROWS + 7) / 8, fb>>>(vv, uu, Wf, bf, A, NROWS);
}

// round 5
// speedup vs baseline: 2.6720x; 2.6613x over previous
#include <cuda_runtime.h>
#include <math.h>
#include <stdint.h>

#define NROWS 50000
#define MPAD  50048     // 391 * 128
#define DIN   1024
#define DC    512
#define DH    256

// ---------------------------------------------------------------------------
// Scratch (__device__ globals; allocation-free rule)
// ---------------------------------------------------------------------------
__device__ float g_t  [(size_t)MPAD * DC];   // h @ [Wv1|Wu1] + b1
__device__ float g_vu [(size_t)MPAD * DC];   // [tanh|sigmoid] halves
__device__ float g_WcT[DC * DIN];            // Wc^T  [512][1024], tf32-rounded
__device__ float g_W1T[DC * DC];             // [Wv1|Wu1]^T [512][512], tf32-rounded
__device__ float g_W2T[DC * DC];             // blockdiag(Wv2,Wu2)^T [512][512], tf32
__device__ float g_b1[DC], g_b2[DC];

// ---------------------------------------------------------------------------
// Helpers
// ---------------------------------------------------------------------------
__device__ __forceinline__ uint32_t smem_to_u32(const void* p) {
    uint32_t a;
    asm("{ .reg .u64 t; cvta.to.shared.u64 t, %1; cvt.u32.u64 %0, t; }" : "=r"(a) : "l"(p));
    return a;
}
__device__ __forceinline__ uint32_t f2tf32(float f) {
    uint32_t r;
    asm("cvt.rna.tf32.f32 %0, %1;" : "=r"(r) : "f"(f));
    return r;
}
__device__ __forceinline__ float f2tf32_f(float f) {
    return __uint_as_float(f2tf32(f));
}
__device__ __forceinline__ void cpa16(uint32_t s, const void* g, uint32_t nbytes) {
    asm volatile("cp.async.cg.shared.global [%0], [%1], 16, %2;"
                 :: "r"(s), "l"(g), "r"(nbytes));
}
#define CP_COMMIT() asm volatile("cp.async.commit_group;" ::: "memory")

// m16n8k8 tf32 MMA, fp32 accumulate (sm_80+, valid on plain sm_100 target)
__device__ __forceinline__ void mma_tf32(float* d, const uint32_t* a, uint32_t b0, uint32_t b1) {
    asm volatile("mma.sync.aligned.m16n8k8.row.col.f32.tf32.tf32.f32 "
                 "{%0,%1,%2,%3}, {%4,%5,%6,%7}, {%8,%9}, {%0,%1,%2,%3};"
                 : "+f"(d[0]), "+f"(d[1]), "+f"(d[2]), "+f"(d[3])
                 : "r"(a[0]), "r"(a[1]), "r"(a[2]), "r"(a[3]), "r"(b0), "r"(b1));
}

// ---------------------------------------------------------------------------
// GEMM: C[M,512-tile] = act(A[M,K] @ Wt^T + bias),  Wt given as [512][K] fp32
// (pre tf32-rounded). A converted to tf32 in-register. CTA tile 128x128,
// BK=16, 2-stage cp.async pipeline, 8 warps (32x64 warp tiles).
// MODE 0: relu   MODE 1: none   MODE 2: tanh (cols<256) / sigmoid (cols>=256)
// ---------------------------------------------------------------------------
#define BM 128
#define BN 128
#define BK 16
#define APITCH 20           // floats per row (BK + 4 pad) -> conflict-free frags

template<int MODE>
__global__ void __launch_bounds__(256, 2)
gemm_tf32(const float* __restrict__ Ag, const float* __restrict__ Bg,
          const float* __restrict__ bias, float* __restrict__ C,
          int M, int K, int nch)
{
    __shared__ float As[2][BM * APITCH];
    __shared__ float Bs[2][BN * APITCH];

    const int tid  = threadIdx.x;
    const int wid  = tid >> 5;
    const int lane = tid & 31;
    const int gr   = lane >> 2;     // group row 0..7
    const int ctg  = lane & 3;      // 0..3
    const int wm   = wid & 3;       // 4 m-slices of 32
    const int wn   = wid >> 2;      // 2 n-slices of 64
    const int bm   = blockIdx.y * BM;
    const int bn   = blockIdx.x * BN;

    const uint32_t uA[2] = { smem_to_u32(&As[0][0]), smem_to_u32(&As[1][0]) };
    const uint32_t uB[2] = { smem_to_u32(&Bs[0][0]), smem_to_u32(&Bs[1][0]) };

    float acc[2][8][4];
    #pragma unroll
    for (int mt = 0; mt < 2; mt++)
        #pragma unroll
        for (int nt = 0; nt < 8; nt++)
            #pragma unroll
            for (int e = 0; e < 4; e++) acc[mt][nt][e] = 0.0f;

    // per-thread load coords: 512 16B chunks per tile, 2 per thread
    auto load_chunk = [&](int s, int k0) {
        #pragma unroll
        for (int j = 0; j < 2; j++) {
            int idx = tid + j * 256;        // 0..511
            int row = idx >> 2;             // 0..127
            int kb  = (idx & 3) * 16;       // byte offset in row: 0,16,32,48
            // A (guarded; zero-fill pad rows via nbytes=0)
            int grow = bm + row;
            uint32_t nb = (grow < M) ? 16u : 0u;
            int arow = (grow < M) ? grow : 0;
            cpa16(uA[s] + row * (APITCH * 4) + kb,
                  (const char*)(Ag + (size_t)arow * K + k0) + kb, nb);
            // B (always valid: 512 rows)
            cpa16(uB[s] + row * (APITCH * 4) + kb,
                  (const char*)(Bg + (size_t)(bn + row) * K + k0) + kb, 16u);
        }
        CP_COMMIT();
    };

    load_chunk(0, 0);
    load_chunk(1, BK);

    for (int i = 0; i < nch; i++) {
        const int s = i & 1;
        if (i + 1 < nch) asm volatile("cp.async.wait_group 1;" ::: "memory");
        else             asm volatile("cp.async.wait_group 0;" ::: "memory");
        __syncthreads();

        #pragma unroll
        for (int ks = 0; ks < 2; ks++) {
            const int kb = ks * 8;
            // A fragments (convert to tf32 here)
            uint32_t a[2][4];
            #pragma unroll
            for (int mt = 0; mt < 2; mt++) {
                const int mb = wm * 32 + mt * 16;
                a[mt][0] = f2tf32(As[s][(mb + gr)     * APITCH + kb + ctg]);
                a[mt][1] = f2tf32(As[s][(mb + gr + 8) * APITCH + kb + ctg]);
                a[mt][2] = f2tf32(As[s][(mb + gr)     * APITCH + kb + ctg + 4]);
                a[mt][3] = f2tf32(As[s][(mb + gr + 8) * APITCH + kb + ctg + 4]);
            }
            // B fragments (pre-rounded in prep)
            #pragma unroll
            for (int nt = 0; nt < 8; nt++) {
                const int nb = wn * 64 + nt * 8 + gr;
                uint32_t b0 = __float_as_uint(Bs[s][nb * APITCH + kb + ctg]);
                uint32_t b1 = __float_as_uint(Bs[s][nb * APITCH + kb + ctg + 4]);
                mma_tf32(acc[0][nt], a[0], b0, b1);
                mma_tf32(acc[1][nt], a[1], b0, b1);
            }
        }
        __syncthreads();
        if (i + 2 < nch) load_chunk(s, (i + 2) * BK);
    }

    // ---- epilogue: bias + activation + guarded float2 stores ----
    #pragma unroll
    for (int nt = 0; nt < 8; nt++) {
        const int col = bn + wn * 64 + nt * 8 + ctg * 2;
        float2 bb = *reinterpret_cast<const float2*>(&bias[col]);
        #pragma unroll
        for (int mt = 0; mt < 2; mt++) {
            const int r0 = bm + wm * 32 + mt * 16 + gr;
            float v[4] = { acc[mt][nt][0] + bb.x, acc[mt][nt][1] + bb.y,
                           acc[mt][nt][2] + bb.x, acc[mt][nt][3] + bb.y };
            #pragma unroll
            for (int e = 0; e < 4; e++) {
                if (MODE == 0)      v[e] = fmaxf(v[e], 0.0f);
                else if (MODE == 2) v[e] = (bn + 64 <= 256) ? tanhf(v[e])
                                                            : (1.0f / (1.0f + expf(-v[e])));
            }
            if (r0 < M)
                *reinterpret_cast<float2*>(&C[(size_t)r0 * 512 + col]) = make_float2(v[0], v[1]);
            if (r0 + 8 < M)
                *reinterpret_cast<float2*>(&C[(size_t)(r0 + 8) * 512 + col]) = make_float2(v[2], v[3]);
        }
    }
}

// ---------------------------------------------------------------------------
// Prep kernels (tiny): transpose + tf32-round weights, concat biases
// ---------------------------------------------------------------------------
__global__ void prep_wc(const float* __restrict__ W, float* __restrict__ T)
{   // W[1024,512] -> T[512][1024]
    int i = blockIdx.x * blockDim.x + threadIdx.x;
    if (i >= DC * DIN) return;
    int n = i / DIN, k = i % DIN;
    T[i] = f2tf32_f(W[(size_t)k * DC + n]);
}
__global__ void prep_w1(const float* __restrict__ Wv, const float* __restrict__ Wu,
                        float* __restrict__ T)
{   // [Wv1|Wu1]^T -> T[512][512]
    int i = blockIdx.x * blockDim.x + threadIdx.x;
    if (i >= DC * DC) return;
    int n = i / DC, k = i % DC;
    float v = (n < DH) ? Wv[(size_t)k * DH + n] : Wu[(size_t)k * DH + (n - DH)];
    T[i] = f2tf32_f(v);
}
__global__ void prep_w2(const float* __restrict__ Wv, const float* __restrict__ Wu,
                        float* __restrict__ T)
{   // blockdiag(Wv2, Wu2)^T -> T[512][512]
    int i = blockIdx.x * blockDim.x + threadIdx.x;
    if (i >= DC * DC) return;
    int n = i / DC, k = i % DC;
    float v = 0.0f;
    if (n < DH && k < DH)        v = Wv[(size_t)k * DH + n];
    else if (n >= DH && k >= DH) v = Wu[(size_t)(k - DH) * DH + (n - DH)];
    T[i] = f2tf32_f(v);
}
__global__ void prep_bias(const float* __restrict__ ba, const float* __restrict__ bb,
                          float* __restrict__ out)
{
    int i = blockIdx.x * blockDim.x + threadIdx.x;
    if (i < DC) out[i] = (i < DH) ? ba[i] : bb[i - DH];
}

// ---------------------------------------------------------------------------
// Final head: A[row,:] = (v ∘ u) @ Wf + bf, v = vu[:, :256], u = vu[:, 256:]
// ---------------------------------------------------------------------------
__global__ void gated_final(const float* __restrict__ vu, const float* __restrict__ Wf,
                            const float* __restrict__ bf, float* __restrict__ out, int M)
{
    int row = blockIdx.x * blockDim.y + threadIdx.y;
    if (row >= M) return;
    int lane = threadIdx.x;
    const float* vr = vu + (size_t)row * 512;
    const float* ur = vr + 256;
    float a0 = 0.f, a1 = 0.f;
    #pragma unroll
    for (int c = lane; c < DH; c += 32) {
        float g = vr[c] * ur[c];
        a0 = fmaf(g, Wf[c * 2 + 0], a0);
        a1 = fmaf(g, Wf[c * 2 + 1], a1);
    }
    #pragma unroll
    for (int off = 16; off; off >>= 1) {
        a0 += __shfl_down_sync(0xffffffffu, a0, off);
        a1 += __shfl_down_sync(0xffffffffu, a1, off);
    }
    if (lane == 0) {
        out[(size_t)row * 2 + 0] = a0 + bf[0];
        out[(size_t)row * 2 + 1] = a1 + bf[1];
    }
}

// ---------------------------------------------------------------------------
extern "C" void kernel_launch(void* const* d_in, const int* in_sizes, int n_in,
                              void* d_out, int out_size)
{
    (void)in_sizes; (void)n_in; (void)out_size;
    const float* X   = (const float*)d_in[0];
    const float* Wc  = (const float*)d_in[1];
    const float* bc  = (const float*)d_in[2];
    const float* Wv1 = (const float*)d_in[3];
    const float* bv1 = (const float*)d_in[4];
    const float* Wv2 = (const float*)d_in[5];
    const float* bv2 = (const float*)d_in[6];
    const float* Wu1 = (const float*)d_in[7];
    const float* bu1 = (const float*)d_in[8];
    const float* Wu2 = (const float*)d_in[9];
    const float* bu2 = (const float*)d_in[10];
    const float* Wf  = (const float*)d_in[11];
    const float* bf  = (const float*)d_in[12];

    float* h = (float*)d_out;                         // [N, 512]
    float* A = (float*)d_out + (size_t)NROWS * DC;    // [N, 2]

    float *t, *vu, *WcT, *W1T, *W2T, *b1, *b2;
    cudaGetSymbolAddress((void**)&t,   g_t);
    cudaGetSymbolAddress((void**)&vu,  g_vu);
    cudaGetSymbolAddress((void**)&WcT, g_WcT);
    cudaGetSymbolAddress((void**)&W1T, g_W1T);
    cudaGetSymbolAddress((void**)&W2T, g_W2T);
    cudaGetSymbolAddress((void**)&b1,  g_b1);
    cudaGetSymbolAddress((void**)&b2,  g_b2);

    // weight prep (tiny)
    prep_wc<<<(DC * DIN + 255) / 256, 256>>>(Wc, WcT);
    prep_w1<<<(DC * DC + 255) / 256, 256>>>(Wv1, Wu1, W1T);
    prep_w2<<<(DC * DC + 255) / 256, 256>>>(Wv2, Wu2, W2T);
    prep_bias<<<2, 256>>>(bv1, bu1, b1);
    prep_bias<<<2, 256>>>(bv2, bu2, b2);

    dim3 grid(DC / BN, MPAD / BM);   // (4, 391)
    dim3 blk(256);

    // GEMM1: h = relu(X @ Wc + bc)            K=1024
    gemm_tf32<0><<<grid, blk>>>(X, WcT, bc, h, NROWS, DIN, DIN / BK);
    // GEMM2: t = h @ [Wv1|Wu1] + [bv1|bu1]    K=512
    gemm_tf32<1><<<grid, blk>>>(h, W1T, b1, t, NROWS, DC, DC / BK);
    // GEMM3: vu = act(t @ blockdiag(Wv2,Wu2) + [bv2|bu2])
    gemm_tf32<2><<<grid, blk>>>(t, W2T, b2, vu, NROWS, DC, DC / BK);
    // final head
    dim3 fb(32, 8);
    gated_final<<<(NROWS + 7) / 8, fb>>>(vu, Wf, bf, A, NROWS);
}

// round 6
// speedup vs baseline: 2.6842x; 1.0046x over previous
#include <cuda_runtime.h>
#include <math.h>
#include <stdint.h>

#define NROWS 50000
#define MPAD  50048     // 391 * 128
#define DIN   1024
#define DC    512
#define DH    256

// ---------------------------------------------------------------------------
// Scratch (__device__ globals; allocation-free rule)
// ---------------------------------------------------------------------------
__device__ float g_t  [(size_t)MPAD * DC];   // h @ [Wv1|Wu1] + b1
__device__ float g_vu [(size_t)MPAD * DC];   // [tanh|sigmoid] halves
__device__ float g_WcT[DC * DIN];            // Wc^T  [512][1024], tf32-rounded
__device__ float g_W1T[DC * DC];             // [Wv1|Wu1]^T [512][512], tf32-rounded
__device__ float g_W2T[DC * DC];             // blockdiag(Wv2,Wu2)^T [512][512], tf32
__device__ float g_b1[DC], g_b2[DC];

// ---------------------------------------------------------------------------
// Helpers
// ---------------------------------------------------------------------------
__device__ __forceinline__ uint32_t smem_to_u32(const void* p) {
    uint32_t a;
    asm("{ .reg .u64 t; cvta.to.shared.u64 t, %1; cvt.u32.u64 %0, t; }" : "=r"(a) : "l"(p));
    return a;
}
__device__ __forceinline__ uint32_t f2tf32(float f) {
    uint32_t r;
    asm("cvt.rna.tf32.f32 %0, %1;" : "=r"(r) : "f"(f));
    return r;
}
__device__ __forceinline__ float f2tf32_f(float f) {
    return __uint_as_float(f2tf32(f));
}
__device__ __forceinline__ void cpa16(uint32_t s, const void* g, uint32_t nbytes) {
    asm volatile("cp.async.cg.shared.global [%0], [%1], 16, %2;"
                 :: "r"(s), "l"(g), "r"(nbytes));
}
#define CP_COMMIT() asm volatile("cp.async.commit_group;" ::: "memory")

// m16n8k8 tf32 MMA, fp32 accumulate (sm_80+, valid on plain sm_100 target)
__device__ __forceinline__ void mma_tf32(float* d, const uint32_t* a, uint32_t b0, uint32_t b1) {
    asm volatile("mma.sync.aligned.m16n8k8.row.col.f32.tf32.tf32.f32 "
                 "{%0,%1,%2,%3}, {%4,%5,%6,%7}, {%8,%9}, {%0,%1,%2,%3};"
                 : "+f"(d[0]), "+f"(d[1]), "+f"(d[2]), "+f"(d[3])
                 : "r"(a[0]), "r"(a[1]), "r"(a[2]), "r"(a[3]), "r"(b0), "r"(b1));
}

// ---------------------------------------------------------------------------
// GEMM: C[M,512-tile] = act(A[M,K] @ Wt^T + bias),  Wt given as [512][K] fp32
// (pre tf32-rounded). A converted to tf32 in-register. CTA tile 128x128,
// BK=16, 2-stage cp.async pipeline, 8 warps (32x64 warp tiles).
// MODE 0: relu   MODE 1: none   MODE 2: tanh (cols<256) / sigmoid (cols>=256)
// ---------------------------------------------------------------------------
#define BM 128
#define BN 128
#define BK 16
#define APITCH 20           // floats per row (BK + 4 pad) -> conflict-free frags

template<int MODE>
__global__ void __launch_bounds__(256, 2)
gemm_tf32(const float* __restrict__ Ag, const float* __restrict__ Bg,
          const float* __restrict__ bias, float* __restrict__ C,
          int M, int K, int nch)
{
    __shared__ float As[2][BM * APITCH];
    __shared__ float Bs[2][BN * APITCH];

    const int tid  = threadIdx.x;
    const int wid  = tid >> 5;
    const int lane = tid & 31;
    const int gr   = lane >> 2;     // group row 0..7
    const int ctg  = lane & 3;      // 0..3
    const int wm   = wid & 3;       // 4 m-slices of 32
    const int wn   = wid >> 2;      // 2 n-slices of 64
    const int bm   = blockIdx.y * BM;
    const int bn   = blockIdx.x * BN;

    const uint32_t uA[2] = { smem_to_u32(&As[0][0]), smem_to_u32(&As[1][0]) };
    const uint32_t uB[2] = { smem_to_u32(&Bs[0][0]), smem_to_u32(&Bs[1][0]) };

    float acc[2][8][4];
    #pragma unroll
    for (int mt = 0; mt < 2; mt++)
        #pragma unroll
        for (int nt = 0; nt < 8; nt++)
            #pragma unroll
            for (int e = 0; e < 4; e++) acc[mt][nt][e] = 0.0f;

    // per-thread load coords: 512 16B chunks per tile, 2 per thread
    auto load_chunk = [&](int s, int k0) {
        #pragma unroll
        for (int j = 0; j < 2; j++) {
            int idx = tid + j * 256;        // 0..511
            int row = idx >> 2;             // 0..127
            int kb  = (idx & 3) * 16;       // byte offset in row: 0,16,32,48
            // A (guarded; zero-fill pad rows via nbytes=0)
            int grow = bm + row;
            uint32_t nb = (grow < M) ? 16u : 0u;
            int arow = (grow < M) ? grow : 0;
            cpa16(uA[s] + row * (APITCH * 4) + kb,
                  (const char*)(Ag + (size_t)arow * K + k0) + kb, nb);
            // B (always valid: 512 rows)
            cpa16(uB[s] + row * (APITCH * 4) + kb,
                  (const char*)(Bg + (size_t)(bn + row) * K + k0) + kb, 16u);
        }
        CP_COMMIT();
    };

    load_chunk(0, 0);
    load_chunk(1, BK);

    for (int i = 0; i < nch; i++) {
        const int s = i & 1;
        if (i + 1 < nch) asm volatile("cp.async.wait_group 1;" ::: "memory");
        else             asm volatile("cp.async.wait_group 0;" ::: "memory");
        __syncthreads();

        #pragma unroll
        for (int ks = 0; ks < 2; ks++) {
            const int kb = ks * 8;
            // A fragments (convert to tf32 here)
            uint32_t a[2][4];
            #pragma unroll
            for (int mt = 0; mt < 2; mt++) {
                const int mb = wm * 32 + mt * 16;
                a[mt][0] = f2tf32(As[s][(mb + gr)     * APITCH + kb + ctg]);
                a[mt][1] = f2tf32(As[s][(mb + gr + 8) * APITCH + kb + ctg]);
                a[mt][2] = f2tf32(As[s][(mb + gr)     * APITCH + kb + ctg + 4]);
                a[mt][3] = f2tf32(As[s][(mb + gr + 8) * APITCH + kb + ctg + 4]);
            }
            // B fragments (pre-rounded in prep)
            #pragma unroll
            for (int nt = 0; nt < 8; nt++) {
                const int nb = wn * 64 + nt * 8 + gr;
                uint32_t b0 = __float_as_uint(Bs[s][nb * APITCH + kb + ctg]);
                uint32_t b1 = __float_as_uint(Bs[s][nb * APITCH + kb + ctg + 4]);
                mma_tf32(acc[0][nt], a[0], b0, b1);
                mma_tf32(acc[1][nt], a[1], b0, b1);
            }
        }
        __syncthreads();
        if (i + 2 < nch) load_chunk(s, (i + 2) * BK);
    }

    // ---- epilogue: bias + activation + guarded float2 stores ----
    #pragma unroll
    for (int nt = 0; nt < 8; nt++) {
        const int col = bn + wn * 64 + nt * 8 + ctg * 2;
        float2 bb = *reinterpret_cast<const float2*>(&bias[col]);
        #pragma unroll
        for (int mt = 0; mt < 2; mt++) {
            const int r0 = bm + wm * 32 + mt * 16 + gr;
            float v[4] = { acc[mt][nt][0] + bb.x, acc[mt][nt][1] + bb.y,
                           acc[mt][nt][2] + bb.x, acc[mt][nt][3] + bb.y };
            #pragma unroll
            for (int e = 0; e < 4; e++) {
                if (MODE == 0)      v[e] = fmaxf(v[e], 0.0f);
                else if (MODE == 2) v[e] = (bn + 64 <= 256) ? tanhf(v[e])
                                                            : (1.0f / (1.0f + expf(-v[e])));
            }
            if (r0 < M)
                *reinterpret_cast<float2*>(&C[(size_t)r0 * 512 + col]) = make_float2(v[0], v[1]);
            if (r0 + 8 < M)
                *reinterpret_cast<float2*>(&C[(size_t)(r0 + 8) * 512 + col]) = make_float2(v[2], v[3]);
        }
    }
}

// ---------------------------------------------------------------------------
// Prep kernels (tiny): transpose + tf32-round weights, concat biases
// ---------------------------------------------------------------------------
__global__ void prep_wc(const float* __restrict__ W, float* __restrict__ T)
{   // W[1024,512] -> T[512][1024]
    int i = blockIdx.x * blockDim.x + threadIdx.x;
    if (i >= DC * DIN) return;
    int n = i / DIN, k = i % DIN;
    T[i] = f2tf32_f(W[(size_t)k * DC + n]);
}
__global__ void prep_w1(const float* __restrict__ Wv, const float* __restrict__ Wu,
                        float* __restrict__ T)
{   // [Wv1|Wu1]^T -> T[512][512]
    int i = blockIdx.x * blockDim.x + threadIdx.x;
    if (i >= DC * DC) return;
    int n = i / DC, k = i % DC;
    float v = (n < DH) ? Wv[(size_t)k * DH + n] : Wu[(size_t)k * DH + (n - DH)];
    T[i] = f2tf32_f(v);
}
__global__ void prep_w2(const float* __restrict__ Wv, const float* __restrict__ Wu,
                        float* __restrict__ T)
{   // blockdiag(Wv2, Wu2)^T -> T[512][512]
    int i = blockIdx.x * blockDim.x + threadIdx.x;
    if (i >= DC * DC) return;
    int n = i / DC, k = i % DC;
    float v = 0.0f;
    if (n < DH && k < DH)        v = Wv[(size_t)k * DH + n];
    else if (n >= DH && k >= DH) v = Wu[(size_t)(k - DH) * DH + (n - DH)];
    T[i] = f2tf32_f(v);
}
__global__ void prep_bias(const float* __restrict__ ba, const float* __restrict__ bb,
                          float* __restrict__ out)
{
    int i = blockIdx.x * blockDim.x + threadIdx.x;
    if (i < DC) out[i] = (i < DH) ? ba[i] : bb[i - DH];
}

// ---------------------------------------------------------------------------
// Final head: A[row,:] = (v ∘ u) @ Wf + bf, v = vu[:, :256], u = vu[:, 256:]
// ---------------------------------------------------------------------------
__global__ void gated_final(const float* __restrict__ vu, const float* __restrict__ Wf,
                            const float* __restrict__ bf, float* __restrict__ out, int M)
{
    int row = blockIdx.x * blockDim.y + threadIdx.y;
    if (row >= M) return;
    int lane = threadIdx.x;
    const float* vr = vu + (size_t)row * 512;
    const float* ur = vr + 256;
    float a0 = 0.f, a1 = 0.f;
    #pragma unroll
    for (int c = lane; c < DH; c += 32) {
        float g = vr[c] * ur[c];
        a0 = fmaf(g, Wf[c * 2 + 0], a0);
        a1 = fmaf(g, Wf[c * 2 + 1], a1);
    }
    #pragma unroll
    for (int off = 16; off; off >>= 1) {
        a0 += __shfl_down_sync(0xffffffffu, a0, off);
        a1 += __shfl_down_sync(0xffffffffu, a1, off);
    }
    if (lane == 0) {
        out[(size_t)row * 2 + 0] = a0 + bf[0];
        out[(size_t)row * 2 + 1] = a1 + bf[1];
    }
}

// ---------------------------------------------------------------------------
extern "C" void kernel_launch(void* const* d_in, const int* in_sizes, int n_in,
                              void* d_out, int out_size)
{
    (void)in_sizes; (void)n_in; (void)out_size;
    const float* X   = (const float*)d_in[0];
    const float* Wc  = (const float*)d_in[1];
    const float* bc  = (const float*)d_in[2];
    const float* Wv1 = (const float*)d_in[3];
    const float* bv1 = (const float*)d_in[4];
    const float* Wv2 = (const float*)d_in[5];
    const float* bv2 = (const float*)d_in[6];
    const float* Wu1 = (const float*)d_in[7];
    const float* bu1 = (const float*)d_in[8];
    const float* Wu2 = (const float*)d_in[9];
    const float* bu2 = (const float*)d_in[10];
    const float* Wf  = (const float*)d_in[11];
    const float* bf  = (const float*)d_in[12];

    float* h = (float*)d_out;                         // [N, 512]
    float* A = (float*)d_out + (size_t)NROWS * DC;    // [N, 2]

    float *t, *vu, *WcT, *W1T, *W2T, *b1, *b2;
    cudaGetSymbolAddress((void**)&t,   g_t);
    cudaGetSymbolAddress((void**)&vu,  g_vu);
    cudaGetSymbolAddress((void**)&WcT, g_WcT);
    cudaGetSymbolAddress((void**)&W1T, g_W1T);
    cudaGetSymbolAddress((void**)&W2T, g_W2T);
    cudaGetSymbolAddress((void**)&b1,  g_b1);
    cudaGetSymbolAddress((void**)&b2,  g_b2);

    // weight prep (tiny)
    prep_wc<<<(DC * DIN + 255) / 256, 256>>>(Wc, WcT);
    prep_w1<<<(DC * DC + 255) / 256, 256>>>(Wv1, Wu1, W1T);
    prep_w2<<<(DC * DC + 255) / 256, 256>>>(Wv2, Wu2, W2T);
    prep_bias<<<2, 256>>>(bv1, bu1, b1);
    prep_bias<<<2, 256>>>(bv2, bu2, b2);

    dim3 grid(DC / BN, MPAD / BM);   // (4, 391)
    dim3 blk(256);

    // GEMM1: h = relu(X @ Wc + bc)            K=1024
    gemm_tf32<0><<<grid, blk>>>(X, WcT, bc, h, NROWS, DIN, DIN / BK);
    // GEMM2: t = h @ [Wv1|Wu1] + [bv1|bu1]    K=512
    gemm_tf32<1><<<grid, blk>>>(h, W1T, b1, t, NROWS, DC, DC / BK);
    // GEMM3: vu = act(t @ blockdiag(Wv2,Wu2) + [bv2|bu2])
    gemm_tf32<2><<<grid, blk>>>(t, W2T, b2, vu, NROWS, DC, DC / BK);
    // final head
    dim3 fb(32, 8);
    gated_final<<<(NROWS + 7) / 8, fb>>>(vu, Wf, bf, A, NROWS);
}

// round 7
// speedup vs baseline: 2.6901x; 1.0022x over previous
#include <cuda_runtime.h>
#include <math.h>
#include <stdint.h>

#define NROWS 50000
#define MPAD  50048     // 391 * 128
#define DIN   1024
#define DC    512
#define DH    256

// ---------------------------------------------------------------------------
// Scratch (__device__ globals; allocation-free rule)
// ---------------------------------------------------------------------------
__device__ float g_t  [(size_t)MPAD * DC];   // h @ [Wv1|Wu1] + b1
__device__ float g_vu [(size_t)MPAD * DC];   // [tanh|sigmoid] halves
__device__ float g_WcT[DC * DIN];            // Wc^T  [512][1024], tf32-rounded
__device__ float g_W1T[DC * DC];             // [Wv1|Wu1]^T [512][512], tf32-rounded
__device__ float g_W2T[DC * DC];             // blockdiag(Wv2,Wu2)^T [512][512], tf32
__device__ float g_b1[DC], g_b2[DC];

// ---------------------------------------------------------------------------
// Helpers
// ---------------------------------------------------------------------------
__device__ __forceinline__ uint32_t smem_to_u32(const void* p) {
    uint32_t a;
    asm("{ .reg .u64 t; cvta.to.shared.u64 t, %1; cvt.u32.u64 %0, t; }" : "=r"(a) : "l"(p));
    return a;
}
__device__ __forceinline__ uint32_t f2tf32(float f) {
    uint32_t r;
    asm("cvt.rna.tf32.f32 %0, %1;" : "=r"(r) : "f"(f));
    return r;
}
__device__ __forceinline__ float f2tf32_f(float f) {
    return __uint_as_float(f2tf32(f));
}
__device__ __forceinline__ void cpa16(uint32_t s, const void* g, uint32_t nbytes) {
    asm volatile("cp.async.cg.shared.global [%0], [%1], 16, %2;"
                 :: "r"(s), "l"(g), "r"(nbytes));
}
#define CP_COMMIT() asm volatile("cp.async.commit_group;" ::: "memory")

// m16n8k8 tf32 MMA, fp32 accumulate (sm_80+, valid on plain sm_100 target)
__device__ __forceinline__ void mma_tf32(float* d, const uint32_t* a, uint32_t b0, uint32_t b1) {
    asm volatile("mma.sync.aligned.m16n8k8.row.col.f32.tf32.tf32.f32 "
                 "{%0,%1,%2,%3}, {%4,%5,%6,%7}, {%8,%9}, {%0,%1,%2,%3};"
                 : "+f"(d[0]), "+f"(d[1]), "+f"(d[2]), "+f"(d[3])
                 : "r"(a[0]), "r"(a[1]), "r"(a[2]), "r"(a[3]), "r"(b0), "r"(b1));
}

// ---------------------------------------------------------------------------
// GEMM: C[M,512-tile] = act(A[M,K] @ Wt^T + bias),  Wt given as [512][K] fp32
// (pre tf32-rounded). A converted to tf32 in-register. CTA tile 128x128,
// BK=16, 2-stage cp.async pipeline, 8 warps (32x64 warp tiles).
// MODE 0: relu   MODE 1: none   MODE 2: tanh (cols<256) / sigmoid (cols>=256)
// ---------------------------------------------------------------------------
#define BM 128
#define BN 128
#define BK 16
#define APITCH 20           // floats per row (BK + 4 pad) -> conflict-free frags

template<int MODE>
__global__ void __launch_bounds__(256, 2)
gemm_tf32(const float* __restrict__ Ag, const float* __restrict__ Bg,
          const float* __restrict__ bias, float* __restrict__ C,
          int M, int K, int nch)
{
    __shared__ float As[2][BM * APITCH];
    __shared__ float Bs[2][BN * APITCH];

    const int tid  = threadIdx.x;
    const int wid  = tid >> 5;
    const int lane = tid & 31;
    const int gr   = lane >> 2;     // group row 0..7
    const int ctg  = lane & 3;      // 0..3
    const int wm   = wid & 3;       // 4 m-slices of 32
    const int wn   = wid >> 2;      // 2 n-slices of 64
    const int bm   = blockIdx.y * BM;
    const int bn   = blockIdx.x * BN;

    const uint32_t uA[2] = { smem_to_u32(&As[0][0]), smem_to_u32(&As[1][0]) };
    const uint32_t uB[2] = { smem_to_u32(&Bs[0][0]), smem_to_u32(&Bs[1][0]) };

    float acc[2][8][4];
    #pragma unroll
    for (int mt = 0; mt < 2; mt++)
        #pragma unroll
        for (int nt = 0; nt < 8; nt++)
            #pragma unroll
            for (int e = 0; e < 4; e++) acc[mt][nt][e] = 0.0f;

    // per-thread load coords: 512 16B chunks per tile, 2 per thread
    auto load_chunk = [&](int s, int k0) {
        #pragma unroll
        for (int j = 0; j < 2; j++) {
            int idx = tid + j * 256;        // 0..511
            int row = idx >> 2;             // 0..127
            int kb  = (idx & 3) * 16;       // byte offset in row: 0,16,32,48
            // A (guarded; zero-fill pad rows via nbytes=0)
            int grow = bm + row;
            uint32_t nb = (grow < M) ? 16u : 0u;
            int arow = (grow < M) ? grow : 0;
            cpa16(uA[s] + row * (APITCH * 4) + kb,
                  (const char*)(Ag + (size_t)arow * K + k0) + kb, nb);
            // B (always valid: 512 rows)
            cpa16(uB[s] + row * (APITCH * 4) + kb,
                  (const char*)(Bg + (size_t)(bn + row) * K + k0) + kb, 16u);
        }
        CP_COMMIT();
    };

    load_chunk(0, 0);
    load_chunk(1, BK);

    for (int i = 0; i < nch; i++) {
        const int s = i & 1;
        if (i + 1 < nch) asm volatile("cp.async.wait_group 1;" ::: "memory");
        else             asm volatile("cp.async.wait_group 0;" ::: "memory");
        __syncthreads();

        #pragma unroll
        for (int ks = 0; ks < 2; ks++) {
            const int kb = ks * 8;
            // A fragments (convert to tf32 here)
            uint32_t a[2][4];
            #pragma unroll
            for (int mt = 0; mt < 2; mt++) {
                const int mb = wm * 32 + mt * 16;
                a[mt][0] = f2tf32(As[s][(mb + gr)     * APITCH + kb + ctg]);
                a[mt][1] = f2tf32(As[s][(mb + gr + 8) * APITCH + kb + ctg]);
                a[mt][2] = f2tf32(As[s][(mb + gr)     * APITCH + kb + ctg + 4]);
                a[mt][3] = f2tf32(As[s][(mb + gr + 8) * APITCH + kb + ctg + 4]);
            }
            // B fragments (pre-rounded in prep)
            #pragma unroll
            for (int nt = 0; nt < 8; nt++) {
                const int nb = wn * 64 + nt * 8 + gr;
                uint32_t b0 = __float_as_uint(Bs[s][nb * APITCH + kb + ctg]);
                uint32_t b1 = __float_as_uint(Bs[s][nb * APITCH + kb + ctg + 4]);
                mma_tf32(acc[0][nt], a[0], b0, b1);
                mma_tf32(acc[1][nt], a[1], b0, b1);
            }
        }
        __syncthreads();
        if (i + 2 < nch) load_chunk(s, (i + 2) * BK);
    }

    // ---- epilogue: bias + activation + guarded float2 stores ----
    #pragma unroll
    for (int nt = 0; nt < 8; nt++) {
        const int col = bn + wn * 64 + nt * 8 + ctg * 2;
        float2 bb = *reinterpret_cast<const float2*>(&bias[col]);
        #pragma unroll
        for (int mt = 0; mt < 2; mt++) {
            const int r0 = bm + wm * 32 + mt * 16 + gr;
            float v[4] = { acc[mt][nt][0] + bb.x, acc[mt][nt][1] + bb.y,
                           acc[mt][nt][2] + bb.x, acc[mt][nt][3] + bb.y };
            #pragma unroll
            for (int e = 0; e < 4; e++) {
                if (MODE == 0)      v[e] = fmaxf(v[e], 0.0f);
                else if (MODE == 2) v[e] = (bn + 64 <= 256) ? tanhf(v[e])
                                                            : (1.0f / (1.0f + expf(-v[e])));
            }
            if (r0 < M)
                *reinterpret_cast<float2*>(&C[(size_t)r0 * 512 + col]) = make_float2(v[0], v[1]);
            if (r0 + 8 < M)
                *reinterpret_cast<float2*>(&C[(size_t)(r0 + 8) * 512 + col]) = make_float2(v[2], v[3]);
        }
    }
}

// ---------------------------------------------------------------------------
// Prep kernels (tiny): transpose + tf32-round weights, concat biases
// ---------------------------------------------------------------------------
__global__ void prep_wc(const float* __restrict__ W, float* __restrict__ T)
{   // W[1024,512] -> T[512][1024]
    int i = blockIdx.x * blockDim.x + threadIdx.x;
    if (i >= DC * DIN) return;
    int n = i / DIN, k = i % DIN;
    T[i] = f2tf32_f(W[(size_t)k * DC + n]);
}
__global__ void prep_w1(const float* __restrict__ Wv, const float* __restrict__ Wu,
                        float* __restrict__ T)
{   // [Wv1|Wu1]^T -> T[512][512]
    int i = blockIdx.x * blockDim.x + threadIdx.x;
    if (i >= DC * DC) return;
    int n = i / DC, k = i % DC;
    float v = (n < DH) ? Wv[(size_t)k * DH + n] : Wu[(size_t)k * DH + (n - DH)];
    T[i] = f2tf32_f(v);
}
__global__ void prep_w2(const float* __restrict__ Wv, const float* __restrict__ Wu,
                        float* __restrict__ T)
{   // blockdiag(Wv2, Wu2)^T -> T[512][512]
    int i = blockIdx.x * blockDim.x + threadIdx.x;
    if (i >= DC * DC) return;
    int n = i / DC, k = i % DC;
    float v = 0.0f;
    if (n < DH && k < DH)        v = Wv[(size_t)k * DH + n];
    else if (n >= DH && k >= DH) v = Wu[(size_t)(k - DH) * DH + (n - DH)];
    T[i] = f2tf32_f(v);
}
__global__ void prep_bias(const float* __restrict__ ba, const float* __restrict__ bb,
                          float* __restrict__ out)
{
    int i = blockIdx.x * blockDim.x + threadIdx.x;
    if (i < DC) out[i] = (i < DH) ? ba[i] : bb[i - DH];
}

// ---------------------------------------------------------------------------
// Final head: A[row,:] = (v ∘ u) @ Wf + bf, v = vu[:, :256], u = vu[:, 256:]
// ---------------------------------------------------------------------------
__global__ void gated_final(const float* __restrict__ vu, const float* __restrict__ Wf,
                            const float* __restrict__ bf, float* __restrict__ out, int M)
{
    int row = blockIdx.x * blockDim.y + threadIdx.y;
    if (row >= M) return;
    int lane = threadIdx.x;
    const float* vr = vu + (size_t)row * 512;
    const float* ur = vr + 256;
    float a0 = 0.f, a1 = 0.f;
    #pragma unroll
    for (int c = lane; c < DH; c += 32) {
        float g = vr[c] * ur[c];
        a0 = fmaf(g, Wf[c * 2 + 0], a0);
        a1 = fmaf(g, Wf[c * 2 + 1], a1);
    }
    #pragma unroll
    for (int off = 16; off; off >>= 1) {
        a0 += __shfl_down_sync(0xffffffffu, a0, off);
        a1 += __shfl_down_sync(0xffffffffu, a1, off);
    }
    if (lane == 0) {
        out[(size_t)row * 2 + 0] = a0 + bf[0];
        out[(size_t)row * 2 + 1] = a1 + bf[1];
    }
}

// ---------------------------------------------------------------------------
extern "C" void kernel_launch(void* const* d_in, const int* in_sizes, int n_in,
                              void* d_out, int out_size)
{
    (void)in_sizes; (void)n_in; (void)out_size;
    const float* X   = (const float*)d_in[0];
    const float* Wc  = (const float*)d_in[1];
    const float* bc  = (const float*)d_in[2];
    const float* Wv1 = (const float*)d_in[3];
    const float* bv1 = (const float*)d_in[4];
    const float* Wv2 = (const float*)d_in[5];
    const float* bv2 = (const float*)d_in[6];
    const float* Wu1 = (const float*)d_in[7];
    const float* bu1 = (const float*)d_in[8];
    const float* Wu2 = (const float*)d_in[9];
    const float* bu2 = (const float*)d_in[10];
    const float* Wf  = (const float*)d_in[11];
    const float* bf  = (const float*)d_in[12];

    float* h = (float*)d_out;                         // [N, 512]
    float* A = (float*)d_out + (size_t)NROWS * DC;    // [N, 2]

    float *t, *vu, *WcT, *W1T, *W2T, *b1, *b2;
    cudaGetSymbolAddress((void**)&t,   g_t);
    cudaGetSymbolAddress((void**)&vu,  g_vu);
    cudaGetSymbolAddress((void**)&WcT, g_WcT);
    cudaGetSymbolAddress((void**)&W1T, g_W1T);
    cudaGetSymbolAddress((void**)&W2T, g_W2T);
    cudaGetSymbolAddress((void**)&b1,  g_b1);
    cudaGetSymbolAddress((void**)&b2,  g_b2);

    // weight prep (tiny)
    prep_wc<<<(DC * DIN + 255) / 256, 256>>>(Wc, WcT);
    prep_w1<<<(DC * DC + 255) / 256, 256>>>(Wv1, Wu1, W1T);
    prep_w2<<<(DC * DC + 255) / 256, 256>>>(Wv2, Wu2, W2T);
    prep_bias<<<2, 256>>>(bv1, bu1, b1);
    prep_bias<<<2, 256>>>(bv2, bu2, b2);

    dim3 grid(DC / BN, MPAD / BM);   // (4, 391)
    dim3 blk(256);

    // GEMM1: h = relu(X @ Wc + bc)            K=1024
    gemm_tf32<0><<<grid, blk>>>(X, WcT, bc, h, NROWS, DIN, DIN / BK);
    // GEMM2: t = h @ [Wv1|Wu1] + [bv1|bu1]    K=512
    gemm_tf32<1><<<grid, blk>>>(h, W1T, b1, t, NROWS, DC, DC / BK);
    // GEMM3: vu = act(t @ blockdiag(Wv2,Wu2) + [bv2|bu2])
    gemm_tf32<2><<<grid, blk>>>(t, W2T, b2, vu, NROWS, DC, DC / BK);
    // final head
    dim3 fb(32, 8);
    gated_final<<<(NROWS + 7) / 8, fb>>>(vu, Wf, bf, A, NROWS);
}